// round 12
// baseline (speedup 1.0000x reference)
#include <cuda_runtime.h>
#include <cuda_bf16.h>
#include <math.h>

#define TWO_PI_F 6.283185307179586f
#define EPS_F 1e-8f

// -------- device scratch (no allocation allowed) --------
// g_notident: 0 => Sigma == I. Statically 0; written (0 -> 1) only when
// Sigma != I — a pure function of the input, so no reset needed.
__device__ int g_notident = 0;
// g_done: completion ticket counter. The last block resets it to 0, so the
// kernel is replay-deterministic under CUDA graph timing.
__device__ unsigned int g_done = 0;
// Global scratch for the cold-path Gauss-Jordan (only last block touches it).
__device__ float g_A[64 * 130];

// ============================================================
// Single fused kernel.
// Hot path (Sigma == I): q = ||x - mu||^2, det = 1, streamed at
// HBM ceiling. First 2 lanes of blocks 0..511 verify one float4 of
// Sigma each (16 KB, amortized inside the 260 MB stream), setting
// g_notident on mismatch.
// Completion: every block takes a ticket; the last block (all
// writes + checks complete) recomputes everything alone if
// g_notident was set (cold, never on this dataset), then resets
// g_done for the next graph replay.
//
// Layout: one warp handles 16 samples (4 KB = 256 float4):
//   lane l front-batches float4 #(l + 32*j), j = 0..7 (MLP = 8).
//   float4 f belongs to sample f/16 => load j of lane l belongs to
//   sample s0 + 2*j + (l>>4).
// 16-lane butterfly reduction over hl = l&15; lanes 0 and 16 write
// 8 outputs each.
// ============================================================
__global__ __launch_bounds__(256)
void nll_fused_kernel(const float* __restrict__ samples,
                      const float* __restrict__ Phi,
                      const float* __restrict__ mu,
                      const float* __restrict__ Sigma,
                      float* __restrict__ out, int N) {
    // ---- distributed Sigma identity check ----
    if (threadIdx.x < 2 && blockIdx.x < 512) {
        const int f = blockIdx.x * 2 + threadIdx.x;     // float4 index 0..1023
        const float4 v = reinterpret_cast<const float4*>(Sigma)[f];
        const int e0 = f * 4, e1 = f * 4 + 1, e2 = f * 4 + 2, e3 = f * 4 + 3;
        const float x0 = ((e0 >> 6) == (e0 & 63)) ? 1.0f : 0.0f;
        const float x1 = ((e1 >> 6) == (e1 & 63)) ? 1.0f : 0.0f;
        const float x2 = ((e2 >> 6) == (e2 & 63)) ? 1.0f : 0.0f;
        const float x3 = ((e3 >> 6) == (e3 & 63)) ? 1.0f : 0.0f;
        if (v.x != x0 || v.y != x1 || v.z != x2 || v.w != x3)
            atomicExch(&g_notident, 1);
    }

    // ---- speculative fast path ----
    const int warp = (blockIdx.x * blockDim.x + threadIdx.x) >> 5;
    const int lane = threadIdx.x & 31;
    const int s0   = warp * 16;

    const float4* smp = reinterpret_cast<const float4*>(samples);
    const float4* mu4 = reinterpret_cast<const float4*>(mu);

    const int hl = lane & 15;            // half-lane index 0..15
    const float c = Phi[0] * rsqrtf(TWO_PI_F);   // det == 1 on this path

    if (s0 + 16 <= N) {
        const int base = s0 * 16;        // float4 index of chunk start
        // front-batch all 8 global loads (MLP_p1 = 8)
        float4 v[8];
        #pragma unroll
        for (int j = 0; j < 8; j++) v[j] = smp[base + lane + 32 * j];
        float4 m = mu4[hl];

        float acc[8];
        #pragma unroll
        for (int j = 0; j < 8; j++) {
            float d;
            d = v[j].x - m.x; acc[j]  = d * d;
            d = v[j].y - m.y; acc[j] += d * d;
            d = v[j].z - m.z; acc[j] += d * d;
            d = v[j].w - m.w; acc[j] += d * d;
        }

        #pragma unroll
        for (int off = 8; off >= 1; off >>= 1) {
            #pragma unroll
            for (int j = 0; j < 8; j++)
                acc[j] += __shfl_xor_sync(0xffffffffu, acc[j], off);
        }

        if (hl == 0) {
            const int sA = s0 + (lane >> 4);     // lane0 -> s0, lane16 -> s0+1
            #pragma unroll
            for (int j = 0; j < 8; j++)
                out[sA + 2 * j] = -__logf(c * __expf(-0.5f * acc[j]) + EPS_F);
        }
    } else if (s0 < N) {
        // tail (cold; only when N % 16 != 0)
        for (int s = s0 + (lane >> 4); s < N; s += 2) {
            float partial = 0.0f;
            #pragma unroll
            for (int k = 0; k < 4; k++) {
                const float d = samples[s * 64 + hl * 4 + k] - mu[hl * 4 + k];
                partial += d * d;
            }
            float q = partial;
            #pragma unroll
            for (int off = 8; off >= 1; off >>= 1)
                q += __shfl_xor_sync(0xffffffffu, q, off);
            if (hl == 0)
                out[s] = -__logf(c * __expf(-0.5f * q) + EPS_F);
        }
    }

    // ---- completion ticket: detect last block ----
    __shared__ unsigned int s_ticket;
    __threadfence();                 // publish this block's writes + checks
    __syncthreads();                 // all warps in block done
    if (threadIdx.x == 0) s_ticket = atomicAdd(&g_done, 1u);
    __syncthreads();

    if (s_ticket == gridDim.x - 1) {
        // last block: all blocks' writes and Sigma checks are visible
        const int flag = atomicAdd(&g_notident, 0);
        if (flag != 0) {
            // ===== cold path: full recompute by this block alone =====
            // (unroll 1 + dynamic indexing => local memory, keeps the hot
            //  path's register budget unaffected)
            const int tid = threadIdx.x;
            const int bd  = blockDim.x;
            __shared__ float s_det;
            __shared__ int   s_piv;
            if (tid == 0) s_det = 1.0f;

            // build augmented [Sigma | I] in global scratch (stride 130)
            #pragma unroll 1
            for (int i = tid; i < 64 * 64; i += bd) {
                int r = i >> 6, cc = i & 63;
                g_A[r * 130 + cc]      = Sigma[i];
                g_A[r * 130 + 64 + cc] = (r == cc) ? 1.0f : 0.0f;
            }
            __syncthreads();

            #pragma unroll 1
            for (int k = 0; k < 64; k++) {
                if (tid == 0) {
                    int   p  = k;
                    float mx = fabsf(g_A[k * 130 + k]);
                    #pragma unroll 1
                    for (int i = k + 1; i < 64; i++) {
                        float v = fabsf(g_A[i * 130 + k]);
                        if (v > mx) { mx = v; p = i; }
                    }
                    s_piv = p;
                }
                __syncthreads();
                const int p = s_piv;
                if (p != k) {
                    #pragma unroll 1
                    for (int cc = tid; cc < 128; cc += bd) {
                        float t = g_A[k * 130 + cc];
                        g_A[k * 130 + cc] = g_A[p * 130 + cc];
                        g_A[p * 130 + cc] = t;
                    }
                }
                __syncthreads();
                const float piv = g_A[k * 130 + k];
                if (tid == 0) s_det *= (p != k) ? -piv : piv;
                const float rpiv = 1.0f / piv;
                #pragma unroll 1
                for (int cc = tid; cc < 128; cc += bd)
                    g_A[k * 130 + cc] *= rpiv;
                __syncthreads();
                // snapshot factor column into the spare scratch column 129
                #pragma unroll 1
                for (int r = tid; r < 64; r += bd)
                    g_A[r * 130 + 129] = g_A[r * 130 + k];
                __syncthreads();
                #pragma unroll 1
                for (int idx = tid; idx < 64 * 128; idx += bd) {
                    int r = idx >> 7, cc = idx & 127;
                    if (r != k)
                        g_A[r * 130 + cc] -= g_A[r * 130 + 129] * g_A[k * 130 + cc];
                }
                __syncthreads();
            }

            const float det = s_det;
            const float cg  = Phi[0] / sqrtf(TWO_PI_F * det);

            // recompute all outputs with the general quadratic form
            #pragma unroll 1
            for (int n = tid; n < N; n += bd) {
                float dv[64];
                #pragma unroll 1
                for (int i = 0; i < 64; i++) dv[i] = samples[n * 64 + i] - mu[i];
                float q = 0.0f;
                #pragma unroll 1
                for (int r = 0; r < 64; r++) {
                    float t = 0.0f;
                    #pragma unroll 1
                    for (int cc = 0; cc < 64; cc++)
                        t += g_A[r * 130 + 64 + cc] * dv[cc];
                    q += t * dv[r];
                }
                out[n] = -logf(cg * expf(-0.5f * q) + EPS_F);
            }
            __syncthreads();
        }
        // reset ticket counter for the next graph replay (deterministic)
        if (threadIdx.x == 0) {
            __threadfence();
            atomicExch(&g_done, 0u);
        }
    }
}

extern "C" void kernel_launch(void* const* d_in, const int* in_sizes, int n_in,
                              void* d_out, int out_size) {
    const float* samples = (const float*)d_in[0];
    const float* Phi     = (const float*)d_in[1];
    const float* mu      = (const float*)d_in[2];
    const float* Sigma   = (const float*)d_in[3];
    float* out = (float*)d_out;

    const int N = out_size;  // number of samples

    // 16 samples per warp, 8 warps per block => 128 samples/block
    const int samples_per_block = 16 * 8;
    const int blocks = (N + samples_per_block - 1) / samples_per_block;
    nll_fused_kernel<<<blocks, 256>>>(samples, Phi, mu, Sigma, out, N);
}